// round 8
// baseline (speedup 1.0000x reference)
#include <cuda_runtime.h>
#include <cuda_fp16.h>
#include <math.h>
#include <stdint.h>

// Problem dims (fixed by the dataset)
#define NT 2048      // tokens (B*S)
#define NE 8         // experts
#define ND 1024      // d_model
#define NF 2048      // d_ff

// -------- scratch (alloc-free: __device__ globals) --------
__device__ int    g_cnt[NE];
__device__ int    g_tok[NE * NT];
__device__ float  g_wgt[NE * NT];
__device__ int2   g_ix[NT];                                   // token -> (e*NT+slot) x2
__device__ float2 g_wx[NT];                                   // token -> weights x2
__device__ __align__(16) __half g_h[(size_t)NE * NT * NF];    // silu(x@W1), fp16
__device__ __align__(16) float  g_y[(size_t)NE * NT * ND];    // GEMM2 dense output
__device__ __align__(16) __half g_w1h[(size_t)NE * ND * NF];  // W1 in fp16
__device__ __align__(16) __half g_w2h[(size_t)NE * NF * ND];  // W2 in fp16
__device__ __align__(16) __half g_xh[NT * ND];                // hidden in fp16

// ---------------------------------------------------------------------------
// fp32 -> fp16 helpers
// ---------------------------------------------------------------------------
union H2U { __half2 h; uint32_t u; };

__device__ __forceinline__ void cvt_store(const float4* __restrict__ src,
                                          uint2* __restrict__ dst, size_t i) {
    float4 v = src[i];
    H2U a, b;
    a.h = __floats2half2_rn(v.x, v.y);
    b.h = __floats2half2_rn(v.z, v.w);
    dst[i] = make_uint2(a.u, b.u);
}

// ---------------------------------------------------------------------------
// Kernel 0: prep — convert hidden to fp16, zero counters
// ---------------------------------------------------------------------------
__global__ void k_prep(const float4* __restrict__ x) {
    int i = blockIdx.x * blockDim.x + threadIdx.x;
    if (i < NT * ND / 4) cvt_store(x, (uint2*)g_xh, (size_t)i);
    if (i < NE) g_cnt[i] = 0;
}

// ---------------------------------------------------------------------------
// Kernel 1: router — softmax over 8 logits, top-2, renormalize, dispatch
// ---------------------------------------------------------------------------
__global__ void k_router(const float* __restrict__ logits) {
    int t = blockIdx.x * blockDim.x + threadIdx.x;
    if (t >= NT) return;
    float l[NE];
#pragma unroll
    for (int e = 0; e < NE; e++) l[e] = logits[t * NE + e];

    int i0 = 0;
#pragma unroll
    for (int e = 1; e < NE; e++) if (l[e] > l[i0]) i0 = e;
    int i1 = -1; float best = -1e30f;
#pragma unroll
    for (int e = 0; e < NE; e++)
        if (e != i0 && l[e] > best) { best = l[e]; i1 = e; }

    float w0 = 1.0f / (1.0f + expf(l[i1] - l[i0]));
    float w1 = 1.0f - w0;

    int s0 = atomicAdd(&g_cnt[i0], 1);
    g_tok[i0 * NT + s0] = t;
    g_wgt[i0 * NT + s0] = w0;
    int s1 = atomicAdd(&g_cnt[i1], 1);
    g_tok[i1 * NT + s1] = t;
    g_wgt[i1 * NT + s1] = w1;

    g_ix[t] = make_int2(i0 * NT + s0, i1 * NT + s1);
    g_wx[t] = make_float2(w0, w1);
}

// ---------------------------------------------------------------------------
// Kernel 2: convert W1 (must finish before GEMM1)
// ---------------------------------------------------------------------------
__global__ void k_cvt_w1(const float4* __restrict__ src) {
    int i = blockIdx.x * blockDim.x + threadIdx.x;
    if (i < NE * ND * NF / 4) cvt_store(src, (uint2*)g_w1h, (size_t)i);
}

// ---------------------------------------------------------------------------
// Kernel 4: combine — out[t] = w0 * y[i0] + w1 * y[i1]
// ---------------------------------------------------------------------------
__global__ void k_comb(float4* __restrict__ out) {
    int i = blockIdx.x * blockDim.x + threadIdx.x;   // over NT*ND/4
    int t = i >> 8;                                  // ND/4 = 256 per token
    int c = i & 255;
    int2   ix = g_ix[t];
    float2 wx = g_wx[t];
    const float4* y = (const float4*)g_y;
    float4 a = y[(size_t)ix.x * 256 + c];
    float4 b = y[(size_t)ix.y * 256 + c];
    float4 r;
    r.x = wx.x * a.x + wx.y * b.x;
    r.y = wx.x * a.y + wx.y * b.y;
    r.z = wx.x * a.z + wx.y * b.z;
    r.w = wx.x * a.w + wx.y * b.w;
    out[i] = r;
}

// ---------------------------------------------------------------------------
// fp16 tensor-core grouped GEMM: mma.sync m16n8k16, CTA tile 128x128,
// macro-stage = 2 x BK32 subtiles (64 k per barrier), 3 macro-stages,
// cp.async pipeline, ldmatrix, XOR-swizzled SMEM.
//   SECOND=false: g_h = silu( gather(g_xh) @ g_w1h[e] )   (K=1024, N=2048)
//                 + extra grid.z slices convert W2 fp32->fp16 concurrently
//   SECOND=true : g_y[e*NT+slot] = g_h @ g_w2h[e]         (K=2048, N=1024)
// ---------------------------------------------------------------------------
#define BK   32
#define SUB  16384   // per subtile: 8KB A (128x32 half) + 8KB B (32x128 half)
#define MSTG (2 * SUB)
#define NSTAGE 3
#define DSMEM (NSTAGE * MSTG)

#define LDSM4(r, a)                                                           \
    asm volatile("ldmatrix.sync.aligned.m8n8.x4.shared.b16 {%0,%1,%2,%3}, [%4];" \
                 : "=r"((r)[0]), "=r"((r)[1]), "=r"((r)[2]), "=r"((r)[3])     \
                 : "r"(a))
#define LDSM4T(r, a)                                                          \
    asm volatile("ldmatrix.sync.aligned.m8n8.x4.trans.shared.b16 {%0,%1,%2,%3}, [%4];" \
                 : "=r"((r)[0]), "=r"((r)[1]), "=r"((r)[2]), "=r"((r)[3])     \
                 : "r"(a))
#define MMA16816(c, a, b0v, b1v)                                              \
    asm volatile("mma.sync.aligned.m16n8k16.row.col.f32.f16.f16.f32 "         \
                 "{%0,%1,%2,%3},{%4,%5,%6,%7},{%8,%9},{%0,%1,%2,%3};"         \
                 : "+f"((c)[0]), "+f"((c)[1]), "+f"((c)[2]), "+f"((c)[3])     \
                 : "r"((a)[0]), "r"((a)[1]), "r"((a)[2]), "r"((a)[3]),        \
                   "r"(b0v), "r"(b1v))

// Subtile-relative byte offsets (16B chunks, XOR-swizzled):
//   A(m 0..127, kc 0..3):  (m>>1)*128 + ((((m&1)<<2)|kc) ^ ((m>>1)&7))*16
//   B(k 0..31,  n8 0..15): 8192 + k*256 + ((n8 ^ (k&7)))*16
__device__ __forceinline__ uint32_t a_off(int m, int kc) {
    return (uint32_t)((m >> 1) * 128 + (((((m & 1) << 2) | kc) ^ ((m >> 1) & 7)) * 16));
}
__device__ __forceinline__ uint32_t b_off(int k, int n8) {
    return (uint32_t)(8192 + k * 256 + ((n8 ^ (k & 7)) * 16));
}

template<int KTOT, int LDB, bool SECOND>
__global__ __launch_bounds__(256, 2)
void k_gemm_h(const float4* __restrict__ w2src)
{
    // ---- piggy-backed W2 conversion CTAs (GEMM1 launch only) --------------
    if (!SECOND && blockIdx.z >= NE) {
        const int slice = blockIdx.z - NE;                 // 0..7
        const int cta   = blockIdx.y * 16 + blockIdx.x;    // 0..255
        size_t base = (((size_t)slice * 256 + cta) * 8) * 256 + threadIdx.x;
        uint2* dst = (uint2*)g_w2h;
#pragma unroll
        for (int r = 0; r < 8; r++)
            cvt_store(w2src, dst, base + (size_t)r * 256);
        return;
    }

    const int e   = blockIdx.z;
    const int cnt = g_cnt[e];
    const int m0  = blockIdx.x * 128;
    if (m0 >= cnt) return;
    const int n0  = blockIdx.y * 128;

    extern __shared__ __align__(128) char smem[];
    const uint32_t sb = (uint32_t)__cvta_generic_to_shared(smem);

    const int tid  = threadIdx.x;
    const int wid  = tid >> 5;
    const int lane = tid & 31;
    const int wm   = wid >> 1;      // 0..3  m quarter (32 rows)
    const int wn   = wid & 1;       // 0..1  n half (64 cols)
    const int gp   = lane >> 2;     // 0..7
    const int tig  = lane & 3;      // 0..3

    // ---- loader state (per subtile: 2 A chunks + 2 B chunks of 16B) -------
    const int kc  = tid & 3;          // A k-chunk (8 halves)
    const int mA  = tid >> 2;         // A row 0..63 (and +64)
    const int n8  = tid & 15;         // B n-chunk
    const int kB  = tid >> 4;         // B k-row 0..15 (and +16)

    const __half* ap0; const __half* ap1;
    int sz0, sz1;
    {
        int ra = m0 + mA, rb = ra + 64;
        if (SECOND) {
            ap0 = g_h + ((size_t)e * NT + ra) * NF + kc * 8;
            ap1 = g_h + ((size_t)e * NT + rb) * NF + kc * 8;
        } else {
            int ta = (ra < cnt) ? g_tok[e * NT + ra] : 0;
            int tb = (rb < cnt) ? g_tok[e * NT + rb] : 0;
            ap0 = g_xh + (size_t)ta * ND + kc * 8;
            ap1 = g_xh + (size_t)tb * ND + kc * 8;
        }
        sz0 = (ra < cnt) ? 16 : 0;
        sz1 = (rb < cnt) ? 16 : 0;
    }
    const __half* Bh  = SECOND ? g_w2h : g_w1h;
    const __half* bp0 = Bh + (size_t)e * KTOT * LDB + n0 + (size_t)kB * LDB + n8 * 8;
    const __half* bp1 = bp0 + (size_t)16 * LDB;

    const uint32_t ad0 = a_off(mA, kc);
    const uint32_t ad1 = a_off(mA + 64, kc);
    const uint32_t bd0 = b_off(kB, n8);
    const uint32_t bd1 = bd0 + 4096;              // (k+16)&7 == k&7

    // ---- fragment smem offsets (subtile-relative), precomputed ------------
    const int lf = lane & 15, lh = lane >> 4;
    uint32_t aoff[2][2];  // [fi][ks]
#pragma unroll
    for (int fi = 0; fi < 2; fi++)
#pragma unroll
        for (int ks = 0; ks < 2; ks++)
            aoff[fi][ks] = a_off(wm * 32 + fi * 16 + lf, ks * 2 + lh);
    uint32_t boff[2][4];  // [ks][fjp]
#pragma unroll
    for (int ks = 0; ks < 2; ks++)
#pragma unroll
        for (int fjp = 0; fjp < 4; fjp++)
            boff[ks][fjp] = b_off(ks * 16 + lf, wn * 8 + fjp * 2 + lh);

    float acc[2][8][4];
#pragma unroll
    for (int i = 0; i < 2; i++)
#pragma unroll
        for (int j = 0; j < 8; j++)
#pragma unroll
            for (int c = 0; c < 4; c++) acc[i][j][c] = 0.0f;

    const int KT2 = KTOT / (2 * BK);    // macro iterations (64 k each)

    // ---- macro-stage loader (2 subtiles) ----------------------------------
    auto load_macro = [&](int s, int kt2) {
#pragma unroll
        for (int sub = 0; sub < 2; sub++) {
            const uint32_t base = sb + (uint32_t)s * MSTG + (uint32_t)sub * SUB;
            const int k0 = (kt2 * 2 + sub) * BK;
            asm volatile("cp.async.cg.shared.global [%0], [%1], 16, %2;"
                         :: "r"(base + ad0), "l"(ap0 + k0), "r"(sz0));
            asm volatile("cp.async.cg.shared.global [%0], [%1], 16, %2;"
                         :: "r"(base + ad1), "l"(ap1 + k0), "r"(sz1));
            asm volatile("cp.async.cg.shared.global [%0], [%1], 16;"
                         :: "r"(base + bd0), "l"(bp0 + (size_t)k0 * LDB));
            asm volatile("cp.async.cg.shared.global [%0], [%1], 16;"
                         :: "r"(base + bd1), "l"(bp1 + (size_t)k0 * LDB));
        }
    };

    load_macro(0, 0);
    asm volatile("cp.async.commit_group;");
    load_macro(1, 1);
    asm volatile("cp.async.commit_group;");

    int s = 0;
    for (int kt2 = 0; kt2 < KT2; kt2++) {
        asm volatile("cp.async.wait_group 1;");
        __syncthreads();

        if (kt2 + 2 < KT2) load_macro((s + 2 == 3) ? 0 : ((s + 2 == 4) ? 1 : s + 2), kt2 + 2);
        asm volatile("cp.async.commit_group;");

#pragma unroll
        for (int sub = 0; sub < 2; sub++) {
            const uint32_t base = sb + (uint32_t)s * MSTG + (uint32_t)sub * SUB;
#pragma unroll
            for (int ks = 0; ks < 2; ks++) {
                uint32_t A0[4], A1[4];
                LDSM4(A0, base + aoff[0][ks]);
                LDSM4(A1, base + aoff[1][ks]);
                uint32_t Bf[8][2];
#pragma unroll
                for (int fjp = 0; fjp < 4; fjp++) {
                    uint32_t r[4];
                    LDSM4T(r, base + boff[ks][fjp]);
                    Bf[fjp * 2 + 0][0] = r[0];  Bf[fjp * 2 + 0][1] = r[1];
                    Bf[fjp * 2 + 1][0] = r[2];  Bf[fjp * 2 + 1][1] = r[3];
                }
#pragma unroll
                for (int fj = 0; fj < 8; fj++) {
                    MMA16816(acc[0][fj], A0, Bf[fj][0], Bf[fj][1]);
                    MMA16816(acc[1][fj], A1, Bf[fj][0], Bf[fj][1]);
                }
            }
        }
        s = (s == 2) ? 0 : s + 1;
    }

    // ---- epilogue ----------------------------------------------------------
    if (!SECOND) {
#pragma unroll
        for (int fi = 0; fi < 2; fi++) {
#pragma unroll
            for (int hh = 0; hh < 2; hh++) {
                int row = m0 + wm * 32 + fi * 16 + hh * 8 + gp;
                if (row < cnt) {
                    __half* Hrow = g_h + ((size_t)e * NT + row) * NF;
#pragma unroll
                    for (int fj = 0; fj < 8; fj++) {
                        int col = n0 + wn * 64 + fj * 8 + 2 * tig;
                        float v0 = acc[fi][fj][2 * hh + 0];
                        float v1 = acc[fi][fj][2 * hh + 1];
                        float s0v = v0 / (1.0f + expf(-v0));
                        float s1v = v1 / (1.0f + expf(-v1));
                        *reinterpret_cast<__half2*>(Hrow + col) =
                            __floats2half2_rn(s0v, s1v);
                    }
                }
            }
        }
    } else {
#pragma unroll
        for (int fi = 0; fi < 2; fi++) {
#pragma unroll
            for (int hh = 0; hh < 2; hh++) {
                int row = m0 + wm * 32 + fi * 16 + hh * 8 + gp;
                if (row < cnt) {
                    float* yrow = g_y + ((size_t)e * NT + row) * ND;
#pragma unroll
                    for (int fj = 0; fj < 8; fj++) {
                        int col = n0 + wn * 64 + fj * 8 + 2 * tig;
                        float2 v;
                        v.x = acc[fi][fj][2 * hh + 0];
                        v.y = acc[fi][fj][2 * hh + 1];
                        *reinterpret_cast<float2*>(yrow + col) = v;
                    }
                }
            }
        }
    }
}

// ---------------------------------------------------------------------------
// launch
// ---------------------------------------------------------------------------
extern "C" void kernel_launch(void* const* d_in, const int* in_sizes, int n_in,
                              void* d_out, int out_size) {
    const float* hidden = (const float*)d_in[0];   // [T, D]
    const float* logits = (const float*)d_in[1];   // [T, E]
    const float* W1     = (const float*)d_in[2];   // [E, D, F]
    const float* W2     = (const float*)d_in[3];   // [E, F, D]
    float* out = (float*)d_out;                    // [T, D]

    static int smem_set = 0;
    if (!smem_set) {
        cudaFuncSetAttribute(k_gemm_h<ND, NF, false>,
                             cudaFuncAttributeMaxDynamicSharedMemorySize, DSMEM);
        cudaFuncSetAttribute(k_gemm_h<NF, ND, true>,
                             cudaFuncAttributeMaxDynamicSharedMemorySize, DSMEM);
        smem_set = 1;
    }

    k_prep<<<(NT * ND / 4 + 255) / 256, 256>>>((const float4*)hidden);
    k_router<<<(NT + 255) / 256, 256>>>(logits);
    k_cvt_w1<<<NE * ND * NF / 4 / 256, 256>>>((const float4*)W1);

    // GEMM1 (z<8) + W2 conversion (z in 8..15) in one launch
    dim3 g1(16, 16, 16);
    k_gemm_h<ND, NF, false><<<g1, 256, DSMEM>>>((const float4*)W2);

    dim3 g2(NT / 128, ND / 128, NE);   // (16, 8, 8)
    k_gemm_h<NF, ND, true><<<g2, 256, DSMEM>>>(nullptr);

    k_comb<<<NT * ND / 4 / 256, 256>>>((float4*)out);
}

// round 9
// speedup vs baseline: 1.0893x; 1.0893x over previous
#include <cuda_runtime.h>
#include <cuda_fp16.h>
#include <math.h>
#include <stdint.h>

// Problem dims (fixed by the dataset)
#define NT 2048      // tokens (B*S)
#define NE 8         // experts
#define ND 1024      // d_model
#define NF 2048      // d_ff

// -------- scratch (alloc-free: __device__ globals) --------
__device__ int   g_cnt[NE];
__device__ int   g_tok[NE * NT];
__device__ float g_wgt[NE * NT];
__device__ int   g_c1claim[NE];                               // W1 cvt work queue
__device__ int   g_c1done[NE];
__device__ __align__(16) __half g_h[(size_t)NE * NT * NF];    // silu(x@W1), fp16
__device__ __align__(16) __half g_w1h[(size_t)NE * ND * NF];  // W1 in fp16
__device__ __align__(16) __half g_w2h[(size_t)NE * NF * ND];  // W2 in fp16
__device__ __align__(16) __half g_xh[NT * ND];                // hidden in fp16

// W1 conversion chunking: per expert ND*NF/4 = 524288 float4 = 128 chunks x 4096
#define W1_F4_PER_E (ND * NF / 4)
#define W1_NCHUNK   128
#define W1_CHUNK_F4 4096

// ---------------------------------------------------------------------------
// fp32 -> fp16 helpers
// ---------------------------------------------------------------------------
union H2U { __half2 h; uint32_t u; };

__device__ __forceinline__ void cvt_store(const float4* __restrict__ src,
                                          uint2* __restrict__ dst, size_t i) {
    float4 v = src[i];
    H2U a, b;
    a.h = __floats2half2_rn(v.x, v.y);
    b.h = __floats2half2_rn(v.z, v.w);
    dst[i] = make_uint2(a.u, b.u);
}

// ---------------------------------------------------------------------------
// Kernel 0: prep — zero out, convert hidden to fp16, reset counters
// ---------------------------------------------------------------------------
__global__ void k_prep(float4* __restrict__ out, const float4* __restrict__ x) {
    int i = blockIdx.x * blockDim.x + threadIdx.x;
    if (i < NT * ND / 4) {
        out[i] = make_float4(0.f, 0.f, 0.f, 0.f);
        cvt_store(x, (uint2*)g_xh, (size_t)i);
    }
    if (i < NE) { g_cnt[i] = 0; g_c1claim[i] = 0; g_c1done[i] = 0; }
}

// ---------------------------------------------------------------------------
// Kernel 1: router — softmax over 8 logits, top-2, renormalize, dispatch
// ---------------------------------------------------------------------------
__global__ void k_router(const float* __restrict__ logits) {
    int t = blockIdx.x * blockDim.x + threadIdx.x;
    if (t >= NT) return;
    float l[NE];
#pragma unroll
    for (int e = 0; e < NE; e++) l[e] = logits[t * NE + e];

    int i0 = 0;
#pragma unroll
    for (int e = 1; e < NE; e++) if (l[e] > l[i0]) i0 = e;
    int i1 = -1; float best = -1e30f;
#pragma unroll
    for (int e = 0; e < NE; e++)
        if (e != i0 && l[e] > best) { best = l[e]; i1 = e; }

    float w0 = 1.0f / (1.0f + expf(l[i1] - l[i0]));
    float w1 = 1.0f - w0;

    int s0 = atomicAdd(&g_cnt[i0], 1);
    g_tok[i0 * NT + s0] = t;
    g_wgt[i0 * NT + s0] = w0;
    int s1 = atomicAdd(&g_cnt[i1], 1);
    g_tok[i1 * NT + s1] = t;
    g_wgt[i1 * NT + s1] = w1;
}

// ---------------------------------------------------------------------------
// fp16 tensor-core grouped GEMM: mma.sync m16n8k16, CTA tile 128x128, BK=32,
// 4-stage cp.async pipeline (dynamic smem), ldmatrix, XOR-swizzled SMEM.
//   SECOND=false: g_h = silu( gather(g_xh) @ g_w1h[e] )   (K=1024, N=2048)
//                 gemm CTAs self-serve W1 fp32->fp16 via per-expert queue;
//                 extra grid.z slices convert W2 concurrently
//   SECOND=true : out += wgt * ( g_h @ g_w2h[e] )         (K=2048, N=1024)
// ---------------------------------------------------------------------------
#define BK  32
#define STG 16384    // per stage: 8KB A (128x32 half) + 8KB B (32x128 half)
#define NSTAGE 4
#define DSMEM (NSTAGE * STG)

#define LDSM4(r, a)                                                           \
    asm volatile("ldmatrix.sync.aligned.m8n8.x4.shared.b16 {%0,%1,%2,%3}, [%4];" \
                 : "=r"((r)[0]), "=r"((r)[1]), "=r"((r)[2]), "=r"((r)[3])     \
                 : "r"(a))
#define LDSM4T(r, a)                                                          \
    asm volatile("ldmatrix.sync.aligned.m8n8.x4.trans.shared.b16 {%0,%1,%2,%3}, [%4];" \
                 : "=r"((r)[0]), "=r"((r)[1]), "=r"((r)[2]), "=r"((r)[3])     \
                 : "r"(a))
#define MMA16816(c, a, b0v, b1v)                                              \
    asm volatile("mma.sync.aligned.m16n8k16.row.col.f32.f16.f16.f32 "         \
                 "{%0,%1,%2,%3},{%4,%5,%6,%7},{%8,%9},{%0,%1,%2,%3};"         \
                 : "+f"((c)[0]), "+f"((c)[1]), "+f"((c)[2]), "+f"((c)[3])     \
                 : "r"((a)[0]), "r"((a)[1]), "r"((a)[2]), "r"((a)[3]),        \
                   "r"(b0v), "r"(b1v))

// SMEM layout (stage-relative byte offsets; 16B chunks, XOR-swizzled):
//   A(m 0..127, kc 0..3):  (m>>1)*128 + ((((m&1)<<2)|kc) ^ ((m>>1)&7))*16
//   B(k 0..31,  n8 0..15): 8192 + k*256 + ((n8 ^ (k&7)))*16
__device__ __forceinline__ uint32_t a_off(int m, int kc) {
    return (uint32_t)((m >> 1) * 128 + (((((m & 1) << 2) | kc) ^ ((m >> 1) & 7)) * 16));
}
__device__ __forceinline__ uint32_t b_off(int k, int n8) {
    return (uint32_t)(8192 + k * 256 + ((n8 ^ (k & 7)) * 16));
}

template<int KTOT, int LDB, bool SECOND>
__global__ __launch_bounds__(256, 2)
void k_gemm_h(const float4* __restrict__ w1src,
              const float4* __restrict__ w2src,
              float* __restrict__ outp)
{
    // ---- piggy-backed W2 conversion CTAs (GEMM1 launch only) --------------
    if (!SECOND && blockIdx.z >= NE) {
        const int slice = blockIdx.z - NE;                 // 0..7
        const int cta   = blockIdx.y * 16 + blockIdx.x;    // 0..255
        size_t base = (((size_t)slice * 256 + cta) * 8) * 256 + threadIdx.x;
        uint2* dst = (uint2*)g_w2h;
#pragma unroll
        for (int r = 0; r < 8; r++)
            cvt_store(w2src, dst, base + (size_t)r * 256);
        return;
    }

    const int e   = blockIdx.z;
    const int cnt = g_cnt[e];
    const int m0  = blockIdx.x * 128;
    if (m0 >= cnt) return;
    const int n0  = blockIdx.y * 128;

    const int tid  = threadIdx.x;

    // ---- self-serve W1 conversion for this expert (GEMM1 only) ------------
    if (!SECOND) {
        __shared__ int s_chunk;
        uint2* dst = (uint2*)g_w1h;
        for (;;) {
            if (tid == 0) s_chunk = atomicAdd(&g_c1claim[e], 1);
            __syncthreads();
            int c = s_chunk;
            __syncthreads();
            if (c >= W1_NCHUNK) break;
            size_t base = (size_t)e * W1_F4_PER_E + (size_t)c * W1_CHUNK_F4 + tid;
#pragma unroll
            for (int r = 0; r < W1_CHUNK_F4 / 256; r++)
                cvt_store(w1src, dst, base + (size_t)r * 256);
            __threadfence();
            if (tid == 0) atomicAdd(&g_c1done[e], 1);
        }
        if (tid == 0) {
            while (*((volatile int*)&g_c1done[e]) < W1_NCHUNK) { }
        }
        __syncthreads();
        __threadfence();
    }

    extern __shared__ __align__(128) char smem[];
    const uint32_t sb = (uint32_t)__cvta_generic_to_shared(smem);

    const int wid  = tid >> 5;
    const int lane = tid & 31;
    const int wm   = wid >> 1;      // 0..3  m quarter (32 rows)
    const int wn   = wid & 1;       // 0..1  n half (64 cols)
    const int gp   = lane >> 2;     // 0..7
    const int tig  = lane & 3;      // 0..3

    // ---- loader state (each thread: 2 A chunks + 2 B chunks of 16B) -------
    const int kc  = tid & 3;          // A k-chunk (8 halves)
    const int mA  = tid >> 2;         // A row 0..63 (and +64)
    const int n8  = tid & 15;         // B n-chunk
    const int kB  = tid >> 4;         // B k-row 0..15 (and +16)

    const __half* ap0; const __half* ap1;
    int sz0, sz1;
    {
        int ra = m0 + mA, rb = ra + 64;
        if (SECOND) {
            ap0 = g_h + ((size_t)e * NT + ra) * NF + kc * 8;
            ap1 = g_h + ((size_t)e * NT + rb) * NF + kc * 8;
        } else {
            int ta = (ra < cnt) ? g_tok[e * NT + ra] : 0;
            int tb = (rb < cnt) ? g_tok[e * NT + rb] : 0;
            ap0 = g_xh + (size_t)ta * ND + kc * 8;
            ap1 = g_xh + (size_t)tb * ND + kc * 8;
        }
        sz0 = (ra < cnt) ? 16 : 0;
        sz1 = (rb < cnt) ? 16 : 0;
    }
    const __half* Bh  = SECOND ? g_w2h : g_w1h;
    const __half* bp0 = Bh + (size_t)e * KTOT * LDB + n0 + (size_t)kB * LDB + n8 * 8;
    const __half* bp1 = bp0 + (size_t)16 * LDB;

    const uint32_t ad0 = a_off(mA, kc);
    const uint32_t ad1 = a_off(mA + 64, kc);
    const uint32_t bd0 = b_off(kB, n8);
    const uint32_t bd1 = bd0 + 4096;              // (k+16)&7 == k&7

    // ---- fragment smem offsets (stage-relative), precomputed --------------
    const int lf = lane & 15, lh = lane >> 4;
    uint32_t aoff[2][2];  // [fi][ks]
#pragma unroll
    for (int fi = 0; fi < 2; fi++)
#pragma unroll
        for (int ks = 0; ks < 2; ks++)
            aoff[fi][ks] = a_off(wm * 32 + fi * 16 + lf, ks * 2 + lh);
    uint32_t boff[2][4];  // [ks][fjp]
#pragma unroll
    for (int ks = 0; ks < 2; ks++)
#pragma unroll
        for (int fjp = 0; fjp < 4; fjp++)
            boff[ks][fjp] = b_off(ks * 16 + lf, wn * 8 + fjp * 2 + lh);

    float acc[2][8][4];
#pragma unroll
    for (int i = 0; i < 2; i++)
#pragma unroll
        for (int j = 0; j < 8; j++)
#pragma unroll
            for (int c = 0; c < 4; c++) acc[i][j][c] = 0.0f;

    const int KT = KTOT / BK;

    // ---- stage loader ------------------------------------------------------
    auto load_stage = [&](int s, int kt) {
        const uint32_t base = sb + (uint32_t)s * STG;
        const int k0 = kt * BK;                     // halves
        asm volatile("cp.async.cg.shared.global [%0], [%1], 16, %2;"
                     :: "r"(base + ad0), "l"(ap0 + k0), "r"(sz0));
        asm volatile("cp.async.cg.shared.global [%0], [%1], 16, %2;"
                     :: "r"(base + ad1), "l"(ap1 + k0), "r"(sz1));
        asm volatile("cp.async.cg.shared.global [%0], [%1], 16;"
                     :: "r"(base + bd0), "l"(bp0 + (size_t)k0 * LDB));
        asm volatile("cp.async.cg.shared.global [%0], [%1], 16;"
                     :: "r"(base + bd1), "l"(bp1 + (size_t)k0 * LDB));
    };

    load_stage(0, 0);
    asm volatile("cp.async.commit_group;");
    load_stage(1, 1);
    asm volatile("cp.async.commit_group;");
    load_stage(2, 2);
    asm volatile("cp.async.commit_group;");

    for (int kt = 0; kt < KT; kt++) {
        asm volatile("cp.async.wait_group 2;");
        __syncthreads();

        if (kt + 3 < KT) load_stage((kt + 3) & 3, kt + 3);
        asm volatile("cp.async.commit_group;");

        const uint32_t base = sb + (uint32_t)(kt & 3) * STG;
#pragma unroll
        for (int ks = 0; ks < 2; ks++) {
            uint32_t A0[4], A1[4];
            LDSM4(A0, base + aoff[0][ks]);
            LDSM4(A1, base + aoff[1][ks]);
            uint32_t Bf[8][2];
#pragma unroll
            for (int fjp = 0; fjp < 4; fjp++) {
                uint32_t r[4];
                LDSM4T(r, base + boff[ks][fjp]);
                Bf[fjp * 2 + 0][0] = r[0];  Bf[fjp * 2 + 0][1] = r[1];
                Bf[fjp * 2 + 1][0] = r[2];  Bf[fjp * 2 + 1][1] = r[3];
            }
#pragma unroll
            for (int fj = 0; fj < 8; fj++) {
                MMA16816(acc[0][fj], A0, Bf[fj][0], Bf[fj][1]);
                MMA16816(acc[1][fj], A1, Bf[fj][0], Bf[fj][1]);
            }
        }
    }

    // ---- epilogue ----------------------------------------------------------
    if (!SECOND) {
#pragma unroll
        for (int fi = 0; fi < 2; fi++) {
#pragma unroll
            for (int hh = 0; hh < 2; hh++) {
                int row = m0 + wm * 32 + fi * 16 + hh * 8 + gp;
                if (row < cnt) {
                    __half* Hrow = g_h + ((size_t)e * NT + row) * NF;
#pragma unroll
                    for (int fj = 0; fj < 8; fj++) {
                        int col = n0 + wn * 64 + fj * 8 + 2 * tig;
                        float v0 = acc[fi][fj][2 * hh + 0];
                        float v1 = acc[fi][fj][2 * hh + 1];
                        float s0v = v0 / (1.0f + expf(-v0));
                        float s1v = v1 / (1.0f + expf(-v1));
                        *reinterpret_cast<__half2*>(Hrow + col) =
                            __floats2half2_rn(s0v, s1v);
                    }
                }
            }
        }
    } else {
#pragma unroll
        for (int fi = 0; fi < 2; fi++) {
#pragma unroll
            for (int hh = 0; hh < 2; hh++) {
                int row = m0 + wm * 32 + fi * 16 + hh * 8 + gp;
                if (row < cnt) {
                    float w = g_wgt[e * NT + row];
                    int   t = g_tok[e * NT + row];
                    float* orow = outp + (size_t)t * ND;
#pragma unroll
                    for (int fj = 0; fj < 8; fj++) {
                        int col = n0 + wn * 64 + fj * 8 + 2 * tig;
                        atomicAdd(orow + col + 0, w * acc[fi][fj][2 * hh + 0]);
                        atomicAdd(orow + col + 1, w * acc[fi][fj][2 * hh + 1]);
                    }
                }
            }
        }
    }
}

// ---------------------------------------------------------------------------
// launch
// ---------------------------------------------------------------------------
extern "C" void kernel_launch(void* const* d_in, const int* in_sizes, int n_in,
                              void* d_out, int out_size) {
    const float* hidden = (const float*)d_in[0];   // [T, D]
    const float* logits = (const float*)d_in[1];   // [T, E]
    const float* W1     = (const float*)d_in[2];   // [E, D, F]
    const float* W2     = (const float*)d_in[3];   // [E, F, D]
    float* out = (float*)d_out;                    // [T, D]

    static int smem_set = 0;
    if (!smem_set) {
        cudaFuncSetAttribute(k_gemm_h<ND, NF, false>,
                             cudaFuncAttributeMaxDynamicSharedMemorySize, DSMEM);
        cudaFuncSetAttribute(k_gemm_h<NF, ND, true>,
                             cudaFuncAttributeMaxDynamicSharedMemorySize, DSMEM);
        smem_set = 1;
    }

    k_prep<<<(NT * ND / 4 + 255) / 256, 256>>>((float4*)out, (const float4*)hidden);
    k_router<<<(NT + 255) / 256, 256>>>(logits);

    // GEMM1 (z<8, with self-serve W1 conversion) + W2 conversion (z in 8..15)
    dim3 g1(16, 16, 16);
    k_gemm_h<ND, NF, false><<<g1, 256, DSMEM>>>((const float4*)W1, (const float4*)W2, nullptr);

    dim3 g2(NT / 128, ND / 128, NE);   // (16, 8, 8)
    k_gemm_h<NF, ND, true><<<g2, 256, DSMEM>>>(nullptr, nullptr, out);
}